// round 9
// baseline (speedup 1.0000x reference)
#include <cuda_runtime.h>
#include <cstdint>

// DepConv3D R8: FFMA2 lanes = (pixel0, pixel1); both depth slices accumulate
// into the SAME register -> acc 32 regs -> 3 CTAs/SM (24 warps). All 32 oc
// per CTA (no duplicated gating). Weights pre-duplicated (w,w) per slice in
// a global buffer, read via warp-uniform LDG.128 (L1-resident). Features in
// plain smem; pixel-pairs are contiguous float2s; gating = AND with packed
// per-pixel-pair masks.

#define CCH 16
#define HH 512
#define WW 512
#define OCC 32
#define TW 64
#define TH 4
#define FT_ROWS 6
#define SPITCH 68                        // floats per row (cols 0..65 used)
#define SF_FLOATS (CCH*FT_ROWS*SPITCH)   // 6528
#define SD_INTS (FT_ROWS*SPITCH)         // 408

typedef unsigned long long ull;

// [k][i][s][e] : 16B entry = (W_s[2e],W_s[2e],W_s[2e+1],W_s[2e+1])
__device__ float4 g_wd[9 * 16 * 2 * 16];

__global__ void pack_weights_kernel(const float* __restrict__ wgt)
{
    int idx = blockIdx.x * blockDim.x + threadIdx.x;
    if (idx < 9 * 16 * 2 * 16) {
        int e = idx & 15, s = (idx >> 4) & 1, i = (idx >> 5) & 15, k = idx >> 9;
        float w0 = wgt[(((2 * e)     * CCH + i) * 3 + s) * 9 + k];
        float w1 = wgt[(((2 * e + 1) * CCH + i) * 3 + s) * 9 + k];
        g_wd[idx] = make_float4(w0, w0, w1, w1);
    }
}

__global__ __launch_bounds__(256, 3)
void depconv3d_kernel(const float* __restrict__ feat,
                      const int*   __restrict__ depth,
                      float* __restrict__ out)
{
    __shared__ float sF[SF_FLOATS];      // [i][r][c], c <-> gx = x0 + c - 1
    __shared__ int   sD[SD_INTS];

    const int tx = threadIdx.x;          // 0..15 -> px base x0 + 4*tx
    const int ty = threadIdx.y;          // 0..3
    const int tz = threadIdx.z;          // 0..3  -> oc 8*tz..8*tz+7 (uniform)
    const int tid = tx + 16 * ty + 64 * tz;
    const int b  = blockIdx.z;
    const int y0 = blockIdx.y * TH;
    const int x0 = blockIdx.x * TW;

    // ---- depth tile ----
    for (int idx = tid; idx < SD_INTS; idx += 256) {
        int r = idx / SPITCH, c = idx - r * SPITCH;
        int gy = y0 + r - 1, gx = x0 + c - 1;
        int d = 0;
        if (gy >= 0 && gy < HH && gx >= 0 && gx < WW && c < 66)
            d = depth[(b * HH + gy) * WW + gx];
        sD[idx] = d;
    }

    // ---- feature tiles (plain floats) ----
    for (int idx = tid; idx < SF_FLOATS; idx += 256) {
        int c   = idx % SPITCH;
        int rem = idx / SPITCH;
        int r   = rem % FT_ROWS;
        int i   = rem / FT_ROWS;
        int gy = y0 + r - 1, gx = x0 + c - 1;
        float v = 0.f;
        if (gy >= 0 && gy < HH && gx >= 0 && gx < WW && c < 66)
            v = feat[((size_t)(b * CCH + i) * HH + gy) * WW + gx];
        sF[idx] = v;
    }
    __syncthreads();

    // ---- per-pixel 9-bit masks (A: dn==dc-1, B: dn==dc) ----
    unsigned mA[4], mB[4];
    #pragma unroll
    for (int p = 0; p < 4; p++) {
        int dc = sD[(ty + 1) * SPITCH + 4 * tx + p + 1];
        unsigned a = 0, bm = 0;
        #pragma unroll
        for (int k = 0; k < 9; k++) {
            int ky = k / 3, kx = k - ky * 3;
            int dn = sD[(ty + ky) * SPITCH + 4 * tx + p + kx];
            a  |= (unsigned)(dn == dc - 1) << k;
            bm |= (unsigned)(dn == dc)     << k;
        }
        mA[p] = a; mB[p] = bm;
    }

    ull acc[2][8];                       // [pxpair][local oc]
    #pragma unroll
    for (int q = 0; q < 2; q++)
        #pragma unroll
        for (int o = 0; o < 8; o++) acc[q][o] = 0ull;

    const unsigned fw = (unsigned)__cvta_generic_to_shared(sF);
    const float4* wbase = g_wd + 4 * tz;           // e-offset for this oc group

    #pragma unroll 1
    for (int ky = 0; ky < 3; ky++) {
        // pair masks: M[kx][q][s] gates pixels (2q, 2q+1) at tap (ky,kx)
        ull M[3][2][2];
        #pragma unroll
        for (int kx = 0; kx < 3; kx++)
            #pragma unroll
            for (int q = 0; q < 2; q++) {
                int k = ky * 3 + kx;
                unsigned aL = 0u - ((mA[2 * q]     >> k) & 1u);
                unsigned aH = 0u - ((mA[2 * q + 1] >> k) & 1u);
                unsigned bL = 0u - ((mB[2 * q]     >> k) & 1u);
                unsigned bH = 0u - ((mB[2 * q + 1] >> k) & 1u);
                M[kx][q][0] = ((ull)aH << 32) | aL;
                M[kx][q][1] = ((ull)bH << 32) | bL;
            }

        const unsigned frow = fw + (unsigned)(((ty + ky) * SPITCH + 4 * tx) * 4);
        const float4* wky = wbase + (ky * 3) * 512;

        #pragma unroll 2
        for (int i = 0; i < CCH; i++) {
            // feature window cols 4tx..4tx+5 (aligned)
            unsigned fa = frow + (unsigned)(i * FT_ROWS * SPITCH * 4);
            ull P01, P23, P45;
            asm("ld.shared.v2.b64 {%0,%1},[%2];" : "=l"(P01), "=l"(P23) : "r"(fa));
            asm("ld.shared.b64 %0,[%1];" : "=l"(P45) : "r"(fa + 16));
            unsigned c0, c1, c2, c3, c4, c5;
            asm("mov.b64 {%0,%1},%2;" : "=r"(c0), "=r"(c1) : "l"(P01));
            asm("mov.b64 {%0,%1},%2;" : "=r"(c2), "=r"(c3) : "l"(P23));
            asm("mov.b64 {%0,%1},%2;" : "=r"(c4), "=r"(c5) : "l"(P45));
            ull X12, X34;
            asm("mov.b64 %0,{%1,%2};" : "=l"(X12) : "r"(c1), "r"(c2));
            asm("mov.b64 %0,{%1,%2};" : "=l"(X34) : "r"(c3), "r"(c4));
            const ull Q0[3] = {P01, X12, P23};
            const ull Q1[3] = {P23, X34, P45};

            const float4* wi = wky + i * 32;

            #pragma unroll
            for (int kx = 0; kx < 3; kx++) {
                ull GA0 = Q0[kx] & M[kx][0][0];
                ull GA1 = Q1[kx] & M[kx][1][0];
                ull GB0 = Q0[kx] & M[kx][0][1];
                ull GB1 = Q1[kx] & M[kx][1][1];
                const float4* pk = wi + kx * 512;
                #pragma unroll
                for (int j = 0; j < 4; j++) {
                    ull u, v;
                    asm("ld.global.nc.v2.b64 {%0,%1},[%2];"
                        : "=l"(u), "=l"(v) : "l"(pk + j));            // slice A
                    asm("fma.rn.f32x2 %0,%1,%2,%0;" : "+l"(acc[0][2*j])   : "l"(GA0), "l"(u));
                    asm("fma.rn.f32x2 %0,%1,%2,%0;" : "+l"(acc[0][2*j+1]) : "l"(GA0), "l"(v));
                    asm("fma.rn.f32x2 %0,%1,%2,%0;" : "+l"(acc[1][2*j])   : "l"(GA1), "l"(u));
                    asm("fma.rn.f32x2 %0,%1,%2,%0;" : "+l"(acc[1][2*j+1]) : "l"(GA1), "l"(v));
                }
                #pragma unroll
                for (int j = 0; j < 4; j++) {
                    ull u, v;
                    asm("ld.global.nc.v2.b64 {%0,%1},[%2];"
                        : "=l"(u), "=l"(v) : "l"(pk + 16 + j));       // slice B
                    asm("fma.rn.f32x2 %0,%1,%2,%0;" : "+l"(acc[0][2*j])   : "l"(GB0), "l"(u));
                    asm("fma.rn.f32x2 %0,%1,%2,%0;" : "+l"(acc[0][2*j+1]) : "l"(GB0), "l"(v));
                    asm("fma.rn.f32x2 %0,%1,%2,%0;" : "+l"(acc[1][2*j])   : "l"(GB1), "l"(u));
                    asm("fma.rn.f32x2 %0,%1,%2,%0;" : "+l"(acc[1][2*j+1]) : "l"(GB1), "l"(v));
                }
            }
        }
    }

    // ---- epilogue: acc[q][o] = (out_px2q, out_px2q+1) for oc = 8tz+o ----
    const int gx = x0 + 4 * tx;
    const int gy = y0 + ty;
    #pragma unroll
    for (int o = 0; o < 8; o++) {
        float2 q0 = *reinterpret_cast<float2*>(&acc[0][o]);
        float2 q1 = *reinterpret_cast<float2*>(&acc[1][o]);
        float4 st = make_float4(q0.x, q0.y, q1.x, q1.y);
        size_t off = (((size_t)(b * OCC + 8 * tz + o) * HH + gy) * WW) + gx;
        *reinterpret_cast<float4*>(out + off) = st;
    }
}

extern "C" void kernel_launch(void* const* d_in, const int* in_sizes, int n_in,
                              void* d_out, int out_size)
{
    const float* feat  = (const float*)d_in[0];
    const int*   depth = (const int*)d_in[1];
    const float* wgt   = (const float*)d_in[2];
    float* out = (float*)d_out;

    pack_weights_kernel<<<(9 * 16 * 2 * 16 + 255) / 256, 256>>>(wgt);

    dim3 block(16, 4, 4);
    dim3 grid(WW / TW, HH / TH, 4);
    depconv3d_kernel<<<grid, block>>>(feat, depth, out);
}